// round 1
// baseline (speedup 1.0000x reference)
#include <cuda_runtime.h>
#include <math.h>
#include <stdint.h>

#define Bb 4
#define Ll 1024
#define Ee 1024
#define Hh 16
#define DHh 64
#define TOPKk 32

// -------- scratch (no allocs allowed) --------
__device__ float g_q [Bb*Ll*Ee];
__device__ float g_k [Bb*Ll*Ee];
__device__ float g_v [Bb*Ll*Ee];
__device__ float g_ao[Bb*Ll*Ee];

// ============================================================
// GEMM: out[M,N] = X[M,K] @ W[N,K]^T + bias[N]   (fp32)
// 128x128 block tile, BK=16, 256 threads, 8x8 microtile.
// All dims divisible by tiles for this problem (M=4096, N=K=1024).
// ============================================================
#define GBM 128
#define GBN 128
#define GBK 16

__global__ __launch_bounds__(256) void gemm_nt_bias(
    const float* __restrict__ X, const float* __restrict__ W,
    const float* __restrict__ bias, float* __restrict__ out,
    int M, int N, int K)
{
    __shared__ float As[GBK][GBM];
    __shared__ float Bs[GBK][GBN];

    const int tid = threadIdx.x;
    const int bm = blockIdx.y * GBM;
    const int bn = blockIdx.x * GBN;

    const int tr = (tid / 16) * 8;
    const int tc = (tid % 16) * 8;

    const int arow  = tid >> 2;     // 0..63
    const int acol4 = tid & 3;      // float4 slot in 16-wide row

    float acc[8][8] = {};

    for (int k0 = 0; k0 < K; k0 += GBK) {
        #pragma unroll
        for (int r = 0; r < 2; r++) {
            int row = arow + r * 64;
            float4 v = *(const float4*)(X + (size_t)(bm + row) * K + k0 + acol4 * 4);
            As[acol4*4+0][row] = v.x;
            As[acol4*4+1][row] = v.y;
            As[acol4*4+2][row] = v.z;
            As[acol4*4+3][row] = v.w;
        }
        #pragma unroll
        for (int r = 0; r < 2; r++) {
            int row = arow + r * 64;
            float4 v = *(const float4*)(W + (size_t)(bn + row) * K + k0 + acol4 * 4);
            Bs[acol4*4+0][row] = v.x;
            Bs[acol4*4+1][row] = v.y;
            Bs[acol4*4+2][row] = v.z;
            Bs[acol4*4+3][row] = v.w;
        }
        __syncthreads();

        #pragma unroll
        for (int k = 0; k < GBK; k++) {
            float ra[8], rb[8];
            #pragma unroll
            for (int i = 0; i < 8; i++) ra[i] = As[k][tr + i];
            #pragma unroll
            for (int j = 0; j < 8; j++) rb[j] = Bs[k][tc + j];
            #pragma unroll
            for (int i = 0; i < 8; i++)
                #pragma unroll
                for (int j = 0; j < 8; j++)
                    acc[i][j] = fmaf(ra[i], rb[j], acc[i][j]);
        }
        __syncthreads();
    }

    #pragma unroll
    for (int i = 0; i < 8; i++) {
        #pragma unroll
        for (int j = 0; j < 8; j++) {
            out[(size_t)(bm + tr + i) * N + bn + tc + j] = acc[i][j] + bias[bn + tc + j];
        }
    }
}

// ============================================================
// Attention: per block = (b, h, 128-query tile).
//   - score GEMM 128q x 64k per key tile (register microtile 8x8)
//   - per-query running top-32 (value + index) in smem
//   - warp-per-query softmax + sparse V gather epilogue
// ============================================================
#define ATT_QT 128
#define ATT_KT 64
#define ATT_THREADS 128

// smem layout (floats):
//   sQt [64][128]         8192
//   sKt [64][64]          4096
//   sS  [128][65]         8320   (pad -> conflict-free per-query scan)
//   sTV [128][33]         4224   (pad 33 -> conflict-free rescan)
//   sTI [128][33]         4224
#define SM_QT   0
#define SM_KT   (SM_QT + 64*128)
#define SM_S    (SM_KT + 64*64)
#define SM_TV   (SM_S  + 128*65)
#define SM_TI   (SM_TV + 128*33)
#define ATT_SMEM_FLOATS (SM_TI + 128*33)

__global__ __launch_bounds__(ATT_THREADS) void attn_topk_kernel(
    const float* __restrict__ gq, const float* __restrict__ gk,
    const float* __restrict__ gv, float* __restrict__ gao)
{
    extern __shared__ float sm[];
    float* sQt = sm + SM_QT;
    float* sKt = sm + SM_KT;
    float* sS  = sm + SM_S;
    float* sTV = sm + SM_TV;
    int*   sTI = (int*)(sm + SM_TI);

    const int tid = threadIdx.x;
    const int bh  = blockIdx.y;          // 0..63
    const int b   = bh / Hh;
    const int h   = bh % Hh;
    const int l0  = blockIdx.x * ATT_QT; // query tile start

    // load 128 queries x 64 dims, transposed into sQt[d][q]
    for (int idx = tid; idx < ATT_QT * DHh; idx += ATT_THREADS) {
        int qq = idx >> 6;
        int d  = idx & 63;
        sQt[d * ATT_QT + qq] = gq[((size_t)(b * Ll + l0 + qq)) * Ee + h * DHh + d];
    }

    // init per-query top-k
    #pragma unroll
    for (int j = 0; j < TOPKk; j++) {
        sTV[tid * 33 + j] = -INFINITY;
        sTI[tid * 33 + j] = 0;
    }
    float curMin = -INFINITY;
    int   curPos = 0;

    const int ty = tid >> 3;  // 0..15  (query group of 8)
    const int tx = tid & 7;   // 0..7   (key group of 8)

    for (int kt = 0; kt < Ll / ATT_KT; kt++) {
        // load key tile transposed: sKt[d][kk]
        for (int idx = tid; idx < ATT_KT * DHh; idx += ATT_THREADS) {
            int kk = idx >> 6;
            int d  = idx & 63;
            sKt[d * ATT_KT + kk] = gk[((size_t)(b * Ll + kt * ATT_KT + kk)) * Ee + h * DHh + d];
        }
        __syncthreads();

        // 128x64 score tile, 8x8 per thread
        float acc[8][8] = {};
        #pragma unroll 8
        for (int d = 0; d < DHh; d++) {
            float ra[8], rb[8];
            #pragma unroll
            for (int i = 0; i < 8; i++) ra[i] = sQt[d * ATT_QT + ty * 8 + i];
            #pragma unroll
            for (int j = 0; j < 8; j++) rb[j] = sKt[d * ATT_KT + tx * 8 + j];
            #pragma unroll
            for (int i = 0; i < 8; i++)
                #pragma unroll
                for (int j = 0; j < 8; j++)
                    acc[i][j] = fmaf(ra[i], rb[j], acc[i][j]);
        }
        #pragma unroll
        for (int i = 0; i < 8; i++)
            #pragma unroll
            for (int j = 0; j < 8; j++)
                sS[(ty * 8 + i) * 65 + tx * 8 + j] = acc[i][j] * 0.125f; // /sqrt(64)
        __syncthreads();

        // per-thread top-32 update over this tile's 64 scores (thread <-> query)
        #pragma unroll 1
        for (int kk = 0; kk < ATT_KT; kk++) {
            float s = sS[tid * 65 + kk];
            if (s > curMin) {
                sTV[tid * 33 + curPos] = s;
                sTI[tid * 33 + curPos] = kt * ATT_KT + kk;
                float mn = sTV[tid * 33];
                int   mp = 0;
                #pragma unroll
                for (int j = 1; j < TOPKk; j++) {
                    float v = sTV[tid * 33 + j];
                    if (v < mn) { mn = v; mp = j; }
                }
                curMin = mn; curPos = mp;
            }
        }
        __syncthreads();
    }

    // epilogue: warp per query — softmax over 32 + sparse V gather
    const int warp = tid >> 5;
    const int lane = tid & 31;
    for (int qi = warp; qi < ATT_QT; qi += 4) {
        float v  = sTV[qi * 33 + lane];
        int   ki = sTI[qi * 33 + lane];

        float mx = v;
        #pragma unroll
        for (int o = 16; o; o >>= 1) mx = fmaxf(mx, __shfl_xor_sync(0xffffffffu, mx, o));
        float e = expf(v - mx);
        float se = e;
        #pragma unroll
        for (int o = 16; o; o >>= 1) se += __shfl_xor_sync(0xffffffffu, se, o);
        float w = e / se;

        float a0 = 0.f, a1 = 0.f;
        #pragma unroll
        for (int j = 0; j < TOPKk; j++) {
            float wj = __shfl_sync(0xffffffffu, w, j);
            int   kj = __shfl_sync(0xffffffffu, ki, j);
            const float* vr = gv + ((size_t)(b * Ll + kj)) * Ee + h * DHh;
            a0 = fmaf(wj, vr[lane],      a0);
            a1 = fmaf(wj, vr[lane + 32], a1);
        }
        float* op = gao + ((size_t)(b * Ll + l0 + qi)) * Ee + h * DHh;
        op[lane]      = a0;
        op[lane + 32] = a1;
    }
}

// ============================================================
extern "C" void kernel_launch(void* const* d_in, const int* in_sizes, int n_in,
                              void* d_out, int out_size)
{
    const float* Q  = (const float*)d_in[0];
    const float* K_ = (const float*)d_in[1];
    const float* V  = (const float*)d_in[2];
    const float* Wq = (const float*)d_in[3];
    const float* bq = (const float*)d_in[4];
    const float* Wk = (const float*)d_in[5];
    const float* bk = (const float*)d_in[6];
    const float* Wv = (const float*)d_in[7];
    const float* bv = (const float*)d_in[8];
    const float* Wo = (const float*)d_in[9];
    const float* bo = (const float*)d_in[10];
    float* out = (float*)d_out;

    float *gq, *gk, *gv, *gao;
    cudaGetSymbolAddress((void**)&gq,  g_q);
    cudaGetSymbolAddress((void**)&gk,  g_k);
    cudaGetSymbolAddress((void**)&gv,  g_v);
    cudaGetSymbolAddress((void**)&gao, g_ao);

    const int M = Bb * Ll;   // 4096
    const int N = Ee;        // 1024
    const int K = Ee;        // 1024

    dim3 gblock(256);
    dim3 ggrid(N / GBN, M / GBM);  // (8, 32)

    // projections
    gemm_nt_bias<<<ggrid, gblock>>>(Q,  Wq, bq, gq, M, N, K);
    gemm_nt_bias<<<ggrid, gblock>>>(K_, Wk, bk, gk, M, N, K);
    gemm_nt_bias<<<ggrid, gblock>>>(V,  Wv, bv, gv, M, N, K);

    // sparse top-k attention
    size_t attSmem = ATT_SMEM_FLOATS * sizeof(float);  // ~116 KB
    cudaFuncSetAttribute(attn_topk_kernel,
                         cudaFuncAttributeMaxDynamicSharedMemorySize, (int)attSmem);
    dim3 agrid(Ll / ATT_QT, Bb * Hh);  // (8, 64)
    attn_topk_kernel<<<agrid, ATT_THREADS, attSmem>>>(gq, gk, gv, gao);

    // output projection
    gemm_nt_bias<<<ggrid, gblock>>>(gao, Wo, bo, out, M, N, K);
}